// round 14
// baseline (speedup 1.0000x reference)
#include <cuda_runtime.h>
#include <cstdint>

// YOLO decode: persistent single-warp blocks, 3-deep pipeline staged by
// cp.async.bulk (one 10880B bulk copy per tile, mbarrier completion),
// 32-box tiles interleaved across warps, one lane per box, smem-cached
// anchors, packed float4 streaming output stores.
// Inputs: small [104,104,3,85] f32, middle [208,208,3,85] f32,
//         large [416,416,3,85] f32, pre_scale [6,3,2] f32.
// Output: [681408, 6] f32, rows zeroed where conf <= 0.5.

constexpr int N_SMALL  = 104 * 104 * 3;   // 32448  (mult of 32)
constexpr int N_MIDDLE = 208 * 208 * 3;   // 129792 (mult of 32)
constexpr int N_LARGE  = 416 * 416 * 3;   // 519168 (mult of 32)
constexpr int N_TOTAL  = N_SMALL + N_MIDDLE + N_LARGE;  // 681408
constexpr int TILE     = 32;
constexpr int N_TILES  = N_TOTAL / TILE;  // 21294
constexpr int NBLK     = 148 * 6;         // 888 single-warp blocks, 6/SM
constexpr int TOTW     = NBLK;
constexpr int V4T      = TILE * 85 / 4;   // 680 float4 per tile
constexpr int D        = 3;               // pipeline depth
constexpr unsigned TILE_BYTES = TILE * 85 * 4;  // 10880, mult of 16

static __device__ __forceinline__ void mbar_init(uint32_t mbar, uint32_t count) {
    asm volatile("mbarrier.init.shared.b64 [%0], %1;" :: "r"(mbar), "r"(count) : "memory");
}
static __device__ __forceinline__ void mbar_expect_tx(uint32_t mbar, uint32_t bytes) {
    asm volatile("mbarrier.arrive.expect_tx.shared.b64 _, [%0], %1;"
                 :: "r"(mbar), "r"(bytes) : "memory");
}
static __device__ __forceinline__ void bulk_g2s(uint32_t dst_smem, const void* gsrc,
                                                uint32_t bytes, uint32_t mbar) {
    asm volatile("cp.async.bulk.shared::cta.global.mbarrier::complete_tx::bytes "
                 "[%0], [%1], %2, [%3];"
                 :: "r"(dst_smem), "l"(gsrc), "r"(bytes), "r"(mbar) : "memory");
}
static __device__ __forceinline__ void mbar_wait(uint32_t mbar, uint32_t parity) {
    uint32_t done;
    asm volatile("{\n\t.reg .pred p;\n\t"
                 "mbarrier.try_wait.parity.acquire.cta.shared::cta.b64 p, [%1], %2;\n\t"
                 "selp.b32 %0, 1, 0, p;\n\t}"
                 : "=r"(done) : "r"(mbar), "r"(parity) : "memory");
    if (!done) {
        asm volatile("{\n\t.reg .pred P1;\n\t"
                     "WL_%=:\n\t"
                     "mbarrier.try_wait.parity.acquire.cta.shared::cta.b64 P1, [%0], %1, 0x989680;\n\t"
                     "@P1 bra.uni WD_%=;\n\t"
                     "bra.uni WL_%=;\n\t"
                     "WD_%=:\n\t}"
                     :: "r"(mbar), "r"(parity) : "memory");
    }
}

static __device__ __forceinline__ void tile_level(
    int t, const float* small, const float* middle, const float* large,
    const float*& in, int& lvl, int& r0)
{
    const int boxBase = t * TILE;
    if (boxBase < N_SMALL)                 { in = small;  lvl = 0; r0 = boxBase; }
    else if (boxBase < N_SMALL + N_MIDDLE) { in = middle; lvl = 1; r0 = boxBase - N_SMALL; }
    else                                   { in = large;  lvl = 2; r0 = boxBase - N_SMALL - N_MIDDLE; }
}

template<int S, int DECT>
static __device__ __forceinline__ void boxxform(
    int r, float tx, float ty, float tw, float th,
    const float* __restrict__ ps_sm,
    float& x, float& y, float& w, float& h)
{
    const int i = r / (3 * S);
    const int j = (r / 3) % S;
    const int a = r % 3;
    constexpr float invS = 1.0f / (float)S;
    x = (1.0f / (1.0f + __expf(-tx)) + (float)i) * invS;
    y = (1.0f / (1.0f + __expf(-ty)) + (float)j) * invS;
    const float aw = ps_sm[(DECT * 3 + a) * 2 + 0];
    const float ah = ps_sm[(DECT * 3 + a) * 2 + 1];
    w = __expf(tw) * aw * (1.0f / 416.0f);
    h = __expf(th) * ah * (1.0f / 416.0f);
}

__global__ __launch_bounds__(32) void HEAD_kernel(
    const float* __restrict__ small,
    const float* __restrict__ middle,
    const float* __restrict__ large,
    const float* __restrict__ pre_scale,
    float* __restrict__ out)
{
    __shared__ float4 sm[D][V4T];                       // 32640 B
    __shared__ float  so[TILE * 6];                     //   768 B
    __shared__ float  sps[36];                          // anchor cache
    __shared__ alignas(8) unsigned long long mbar[D];   // per-buffer barriers

    const int lane = threadIdx.x;
    const int gw   = blockIdx.x;

    sps[lane] = __ldg(pre_scale + lane);
    if (lane < 4) sps[32 + lane] = __ldg(pre_scale + 32 + lane);

    uint32_t mb[D];
    #pragma unroll
    for (int k = 0; k < D; k++)
        mb[k] = (uint32_t)__cvta_generic_to_shared(&mbar[k]);
    uint32_t sbase[D];
    #pragma unroll
    for (int k = 0; k < D; k++)
        sbase[k] = (uint32_t)__cvta_generic_to_shared(&sm[k][0]);

    if (lane == 0) {
        #pragma unroll
        for (int k = 0; k < D; k++) mbar_init(mb[k], 1);
    }
    asm volatile("fence.proxy.async.shared::cta;" ::: "memory");
    __syncwarp();

    // lane 0 issues one bulk copy for tile t into buffer buf
    auto stage = [&](int t, int buf) {
        if (lane == 0 && t < N_TILES) {
            const float* in; int lvl, r0;
            tile_level(t, small, middle, large, in, lvl, r0);
            mbar_expect_tx(mb[buf], TILE_BYTES);
            bulk_g2s(sbase[buf], in + (size_t)r0 * 85, TILE_BYTES, mb[buf]);
        }
    };

    auto compute = [&](int t, int buf) {
        const float* inu; int lvl, r0;
        tile_level(t, small, middle, large, inu, lvl, r0);

        const float* b = (const float*)&sm[buf][0] + lane * 85;
        const float conf = b[0];
        const float tx = b[1], ty = b[2], tw = b[3], th = b[4];

        // two-chain argmax over 80 logits, first-occurrence tie-break
        float b0 = b[5];  int i0 = 0;
        float b1 = b[6];  int i1 = 1;
        #pragma unroll
        for (int k = 2; k < 80; k += 2) {
            const float v0 = b[5 + k];
            const float v1 = b[6 + k];
            if (v0 > b0) { b0 = v0; i0 = k; }
            if (v1 > b1) { b1 = v1; i1 = k + 1; }
        }
        const int bi = (b1 > b0 || (b1 == b0 && i1 < i0)) ? i1 : i0;

        const int r = r0 + lane;
        float x, y, w, h;
        if (lvl == 0)      boxxform<104, 3>(r, tx, ty, tw, th, sps, x, y, w, h);
        else if (lvl == 1) boxxform<208, 4>(r, tx, ty, tw, th, sps, x, y, w, h);
        else               boxxform<416, 5>(r, tx, ty, tw, th, sps, x, y, w, h);

        const float mk = (conf > 0.5f) ? 1.0f : 0.0f;
        float* o = &so[lane * 6];
        o[0] = x * mk;
        o[1] = y * mk;
        o[2] = w * mk;
        o[3] = h * mk;
        o[4] = (float)bi * mk;
        o[5] = conf * mk;
        __syncwarp();
        float4* og = (float4*)(out + (size_t)t * (TILE * 6));
        __stcs(og + lane, ((const float4*)so)[lane]);
        if (lane < 16) __stcs(og + 32 + lane, ((const float4*)so)[32 + lane]);
    };

    const int t0 = gw;

    #pragma unroll
    for (int k = 0; k < D - 1; k++) stage(t0 + k * TOTW, k);  // buffers 0,1

    uint32_t ph = 0;                     // per-buffer phase-parity bitmask
    int i = 0;
    for (int t = t0; t < N_TILES; t += TOTW, i++) {
        const int buf = i % D;
        mbar_wait(mb[buf], (ph >> buf) & 1u);
        ph ^= (1u << buf);
        __syncwarp();                    // protect so/buffer reuse (ITS)
        compute(t, buf);
        stage(t + (D - 1) * TOTW, (i + D - 1) % D);   // refill oldest buffer
    }
}

extern "C" void kernel_launch(void* const* d_in, const int* in_sizes, int n_in,
                              void* d_out, int out_size)
{
    const float* small     = (const float*)d_in[0];
    const float* middle    = (const float*)d_in[1];
    const float* large     = (const float*)d_in[2];
    const float* pre_scale = (const float*)d_in[3];
    float* out = (float*)d_out;

    HEAD_kernel<<<NBLK, 32>>>(small, middle, large, pre_scale, out);
}

// round 15
// speedup vs baseline: 1.0819x; 1.0819x over previous
#include <cuda_runtime.h>
#include <cstdint>

// YOLO decode — R13 structure with stage-before-compute reordering.
// Persistent single-warp blocks, 3-deep cp.async pipeline, 32-box tiles
// (interleaved), one lane per box, smem-cached anchors, packed float4
// streaming output stores, unguarded 21+tail stage loop.
// Loop body: wait -> syncwarp -> stage(refill oldest) -> compute, so each
// tile's refill copies are in flight during this iteration's compute phase.
// Inputs: small [104,104,3,85] f32, middle [208,208,3,85] f32,
//         large [416,416,3,85] f32, pre_scale [6,3,2] f32.
// Output: [681408, 6] f32, rows zeroed where conf <= 0.5.

constexpr int N_SMALL  = 104 * 104 * 3;   // 32448  (mult of 32)
constexpr int N_MIDDLE = 208 * 208 * 3;   // 129792 (mult of 32)
constexpr int N_LARGE  = 416 * 416 * 3;   // 519168 (mult of 32)
constexpr int N_TOTAL  = N_SMALL + N_MIDDLE + N_LARGE;  // 681408
constexpr int TILE     = 32;
constexpr int N_TILES  = N_TOTAL / TILE;  // 21294
constexpr int NBLK     = 148 * 6;         // 888 single-warp blocks, 6/SM
constexpr int TOTW     = NBLK;            // 888 warps, ~24 tiles each
constexpr int V4T      = TILE * 85 / 4;   // 680 float4 per tile = 21*32 + 8
constexpr int D        = 3;               // pipeline depth (buffers/warp)

static __device__ __forceinline__ void cp16(uint32_t dst_smem, const float4* src) {
    asm volatile("cp.async.cg.shared.global [%0], [%1], 16;\n"
                 :: "r"(dst_smem), "l"(src));
}
static __device__ __forceinline__ void cp_commit() {
    asm volatile("cp.async.commit_group;\n" ::: "memory");
}
template<int N>
static __device__ __forceinline__ void cp_wait() {
    asm volatile("cp.async.wait_group %0;\n" :: "n"(N) : "memory");
}

static __device__ __forceinline__ void tile_level(
    int t, const float* small, const float* middle, const float* large,
    const float*& in, int& lvl, int& r0)
{
    const int boxBase = t * TILE;
    if (boxBase < N_SMALL)                 { in = small;  lvl = 0; r0 = boxBase; }
    else if (boxBase < N_SMALL + N_MIDDLE) { in = middle; lvl = 1; r0 = boxBase - N_SMALL; }
    else                                   { in = large;  lvl = 2; r0 = boxBase - N_SMALL - N_MIDDLE; }
}

template<int S, int DECT>
static __device__ __forceinline__ void boxxform(
    int r, float tx, float ty, float tw, float th,
    const float* __restrict__ ps_sm,     // smem-cached [6,3,2] anchor table
    float& x, float& y, float& w, float& h)
{
    const int i = r / (3 * S);
    const int j = (r / 3) % S;
    const int a = r % 3;
    constexpr float invS = 1.0f / (float)S;
    x = (1.0f / (1.0f + __expf(-tx)) + (float)i) * invS;
    y = (1.0f / (1.0f + __expf(-ty)) + (float)j) * invS;
    const float aw = ps_sm[(DECT * 3 + a) * 2 + 0];
    const float ah = ps_sm[(DECT * 3 + a) * 2 + 1];
    w = __expf(tw) * aw * (1.0f / 416.0f);
    h = __expf(th) * ah * (1.0f / 416.0f);
}

__global__ __launch_bounds__(32) void HEAD_kernel(
    const float* __restrict__ small,
    const float* __restrict__ middle,
    const float* __restrict__ large,
    const float* __restrict__ pre_scale,
    float* __restrict__ out)
{
    __shared__ float4 sm[D][V4T];        // 32640 B
    __shared__ float  so[TILE * 6];      //   768 B output staging
    __shared__ float  sps[36];           // pre_scale cache [6,3,2]

    const int lane = threadIdx.x;
    const int gw   = blockIdx.x;

    // cache the anchor table once
    sps[lane] = __ldg(pre_scale + lane);
    if (lane < 4) sps[32 + lane] = __ldg(pre_scale + 32 + lane);
    __syncwarp();

    uint32_t sbase[D];
    #pragma unroll
    for (int k = 0; k < D; k++)
        sbase[k] = (uint32_t)__cvta_generic_to_shared(&sm[k][0]);

    // stage one tile's copies into buffer `buf`; ALWAYS commits ONE group
    auto stage = [&](int t, int buf) {
        if (t < N_TILES) {
            const float* in; int lvl, r0;
            tile_level(t, small, middle, large, in, lvl, r0);
            const float4* g4 = (const float4*)(in + (size_t)r0 * 85);
            const uint32_t sb = sbase[buf];
            #pragma unroll
            for (int j = 0; j < 21; j++) {           // 21 full rounds, no guard
                const int idx = lane + 32 * j;
                cp16(sb + idx * 16, g4 + idx);
            }
            if (lane < 8) {                          // tail: idx 672..679
                const int idx = 672 + lane;
                cp16(sb + idx * 16, g4 + idx);
            }
        }
        cp_commit();
    };

    auto compute = [&](int t, int buf) {
        const float* inu; int lvl, r0;
        tile_level(t, small, middle, large, inu, lvl, r0);

        const float* b = (const float*)&sm[buf][0] + lane * 85;
        const float conf = b[0];
        const float tx = b[1], ty = b[2], tw = b[3], th = b[4];

        // two-chain argmax over 80 logits, first-occurrence tie-break
        float b0 = b[5];  int i0 = 0;
        float b1 = b[6];  int i1 = 1;
        #pragma unroll
        for (int k = 2; k < 80; k += 2) {
            const float v0 = b[5 + k];
            const float v1 = b[6 + k];
            if (v0 > b0) { b0 = v0; i0 = k; }
            if (v1 > b1) { b1 = v1; i1 = k + 1; }
        }
        const int bi = (b1 > b0 || (b1 == b0 && i1 < i0)) ? i1 : i0;

        const int r = r0 + lane;
        float x, y, w, h;
        if (lvl == 0)      boxxform<104, 3>(r, tx, ty, tw, th, sps, x, y, w, h);
        else if (lvl == 1) boxxform<208, 4>(r, tx, ty, tw, th, sps, x, y, w, h);
        else               boxxform<416, 5>(r, tx, ty, tw, th, sps, x, y, w, h);

        const float mk = (conf > 0.5f) ? 1.0f : 0.0f;
        float* o = &so[lane * 6];
        o[0] = x * mk;
        o[1] = y * mk;
        o[2] = w * mk;
        o[3] = h * mk;
        o[4] = (float)bi * mk;
        o[5] = conf * mk;
        __syncwarp();
        // 32 boxes * 6 floats = 48 float4 -> two coalesced streaming rounds
        float4* og = (float4*)(out + (size_t)t * (TILE * 6));
        __stcs(og + lane, ((const float4*)so)[lane]);
        if (lane < 16) __stcs(og + 32 + lane, ((const float4*)so)[32 + lane]);
    };

    const int t0 = gw;

    #pragma unroll
    for (int k = 0; k < D - 1; k++) stage(t0 + k * TOTW, k);

    int i = 0;
    for (int t = t0; t < N_TILES; t += TOTW, i++) {
        cp_wait<D - 2>();                // tile t's group complete
        __syncwarp();                    // all lanes past prev compute: the
                                         // buffer refilled below was last read
                                         // at iter i-1, now finished
        stage(t + (D - 1) * TOTW, (i + D - 1) % D);  // refill BEFORE compute
        compute(t, i % D);
    }
}

extern "C" void kernel_launch(void* const* d_in, const int* in_sizes, int n_in,
                              void* d_out, int out_size)
{
    const float* small     = (const float*)d_in[0];
    const float* middle    = (const float*)d_in[1];
    const float* large     = (const float*)d_in[2];
    const float* pre_scale = (const float*)d_in[3];
    float* out = (float*)d_out;

    HEAD_kernel<<<NBLK, 32>>>(small, middle, large, pre_scale, out);
}

// round 16
// speedup vs baseline: 1.0888x; 1.0064x over previous
#include <cuda_runtime.h>
#include <cstdint>

// YOLO decode — FINAL (measured best, R13). Persistent single-warp blocks,
// 3-deep cp.async pipeline, 32-box tiles interleaved across warps, one lane
// per box, smem-cached anchors, packed float4 streaming output stores,
// unguarded stage loop (680 copies = 21 full rounds + 8-lane tail).
// Loop body: wait -> syncwarp -> compute -> stage(refill oldest).
// Inputs: small [104,104,3,85] f32, middle [208,208,3,85] f32,
//         large [416,416,3,85] f32, pre_scale [6,3,2] f32.
// Output: [681408, 6] f32, rows zeroed where conf <= 0.5.

constexpr int N_SMALL  = 104 * 104 * 3;   // 32448  (mult of 32)
constexpr int N_MIDDLE = 208 * 208 * 3;   // 129792 (mult of 32)
constexpr int N_LARGE  = 416 * 416 * 3;   // 519168 (mult of 32)
constexpr int N_TOTAL  = N_SMALL + N_MIDDLE + N_LARGE;  // 681408
constexpr int TILE     = 32;
constexpr int N_TILES  = N_TOTAL / TILE;  // 21294
constexpr int NBLK     = 148 * 6;         // 888 single-warp blocks, 6/SM
constexpr int TOTW     = NBLK;            // 888 warps, ~24 tiles each
constexpr int V4T      = TILE * 85 / 4;   // 680 float4 per tile = 21*32 + 8
constexpr int D        = 3;               // pipeline depth (buffers/warp)

static __device__ __forceinline__ void cp16(uint32_t dst_smem, const float4* src) {
    asm volatile("cp.async.cg.shared.global [%0], [%1], 16;\n"
                 :: "r"(dst_smem), "l"(src));
}
static __device__ __forceinline__ void cp_commit() {
    asm volatile("cp.async.commit_group;\n" ::: "memory");
}
template<int N>
static __device__ __forceinline__ void cp_wait() {
    asm volatile("cp.async.wait_group %0;\n" :: "n"(N) : "memory");
}

static __device__ __forceinline__ void tile_level(
    int t, const float* small, const float* middle, const float* large,
    const float*& in, int& lvl, int& r0)
{
    const int boxBase = t * TILE;
    if (boxBase < N_SMALL)                 { in = small;  lvl = 0; r0 = boxBase; }
    else if (boxBase < N_SMALL + N_MIDDLE) { in = middle; lvl = 1; r0 = boxBase - N_SMALL; }
    else                                   { in = large;  lvl = 2; r0 = boxBase - N_SMALL - N_MIDDLE; }
}

template<int S, int DECT>
static __device__ __forceinline__ void boxxform(
    int r, float tx, float ty, float tw, float th,
    const float* __restrict__ ps_sm,     // smem-cached [6,3,2] anchor table
    float& x, float& y, float& w, float& h)
{
    const int i = r / (3 * S);
    const int j = (r / 3) % S;
    const int a = r % 3;
    constexpr float invS = 1.0f / (float)S;
    x = (1.0f / (1.0f + __expf(-tx)) + (float)i) * invS;
    y = (1.0f / (1.0f + __expf(-ty)) + (float)j) * invS;
    const float aw = ps_sm[(DECT * 3 + a) * 2 + 0];
    const float ah = ps_sm[(DECT * 3 + a) * 2 + 1];
    w = __expf(tw) * aw * (1.0f / 416.0f);
    h = __expf(th) * ah * (1.0f / 416.0f);
}

__global__ __launch_bounds__(32) void HEAD_kernel(
    const float* __restrict__ small,
    const float* __restrict__ middle,
    const float* __restrict__ large,
    const float* __restrict__ pre_scale,
    float* __restrict__ out)
{
    __shared__ float4 sm[D][V4T];        // 32640 B
    __shared__ float  so[TILE * 6];      //   768 B output staging
    __shared__ float  sps[36];           // pre_scale cache [6,3,2]

    const int lane = threadIdx.x;
    const int gw   = blockIdx.x;

    // cache the anchor table once
    sps[lane] = __ldg(pre_scale + lane);
    if (lane < 4) sps[32 + lane] = __ldg(pre_scale + 32 + lane);
    __syncwarp();

    uint32_t sbase[D];
    #pragma unroll
    for (int k = 0; k < D; k++)
        sbase[k] = (uint32_t)__cvta_generic_to_shared(&sm[k][0]);

    // stage one tile's copies into buffer `buf`; ALWAYS commits ONE group
    auto stage = [&](int t, int buf) {
        if (t < N_TILES) {
            const float* in; int lvl, r0;
            tile_level(t, small, middle, large, in, lvl, r0);
            const float4* g4 = (const float4*)(in + (size_t)r0 * 85);
            const uint32_t sb = sbase[buf];
            #pragma unroll
            for (int j = 0; j < 21; j++) {           // 21 full rounds, no guard
                const int idx = lane + 32 * j;
                cp16(sb + idx * 16, g4 + idx);
            }
            if (lane < 8) {                          // tail: idx 672..679
                const int idx = 672 + lane;
                cp16(sb + idx * 16, g4 + idx);
            }
        }
        cp_commit();
    };

    auto compute = [&](int t, int buf) {
        const float* inu; int lvl, r0;
        tile_level(t, small, middle, large, inu, lvl, r0);

        const float* b = (const float*)&sm[buf][0] + lane * 85;
        const float conf = b[0];
        const float tx = b[1], ty = b[2], tw = b[3], th = b[4];

        // two-chain argmax over 80 logits, first-occurrence tie-break
        float b0 = b[5];  int i0 = 0;
        float b1 = b[6];  int i1 = 1;
        #pragma unroll
        for (int k = 2; k < 80; k += 2) {
            const float v0 = b[5 + k];
            const float v1 = b[6 + k];
            if (v0 > b0) { b0 = v0; i0 = k; }
            if (v1 > b1) { b1 = v1; i1 = k + 1; }
        }
        const int bi = (b1 > b0 || (b1 == b0 && i1 < i0)) ? i1 : i0;

        const int r = r0 + lane;
        float x, y, w, h;
        if (lvl == 0)      boxxform<104, 3>(r, tx, ty, tw, th, sps, x, y, w, h);
        else if (lvl == 1) boxxform<208, 4>(r, tx, ty, tw, th, sps, x, y, w, h);
        else               boxxform<416, 5>(r, tx, ty, tw, th, sps, x, y, w, h);

        const float mk = (conf > 0.5f) ? 1.0f : 0.0f;
        float* o = &so[lane * 6];
        o[0] = x * mk;
        o[1] = y * mk;
        o[2] = w * mk;
        o[3] = h * mk;
        o[4] = (float)bi * mk;
        o[5] = conf * mk;
        __syncwarp();
        // 32 boxes * 6 floats = 48 float4 -> two coalesced streaming rounds
        float4* og = (float4*)(out + (size_t)t * (TILE * 6));
        __stcs(og + lane, ((const float4*)so)[lane]);
        if (lane < 16) __stcs(og + 32 + lane, ((const float4*)so)[32 + lane]);
    };

    const int t0 = gw;

    #pragma unroll
    for (int k = 0; k < D - 1; k++) stage(t0 + k * TOTW, k);

    int i = 0;
    for (int t = t0; t < N_TILES; t += TOTW, i++) {
        cp_wait<D - 2>();                // tile t's group complete
        __syncwarp();                    // converge + prev-iter smem reuse
        compute(t, i % D);
        stage(t + (D - 1) * TOTW, (i + D - 1) % D);  // refill oldest buffer
    }
}

extern "C" void kernel_launch(void* const* d_in, const int* in_sizes, int n_in,
                              void* d_out, int out_size)
{
    const float* small     = (const float*)d_in[0];
    const float* middle    = (const float*)d_in[1];
    const float* large     = (const float*)d_in[2];
    const float* pre_scale = (const float*)d_in[3];
    float* out = (float*)d_out;

    HEAD_kernel<<<NBLK, 32>>>(small, middle, large, pre_scale, out);
}

// round 17
// speedup vs baseline: 1.1141x; 1.0233x over previous
#include <cuda_runtime.h>
#include <cstdint>

// YOLO decode — R13 structure (measured best) + 4-chain argmax (shorter
// serial FSEL dependency). Persistent single-warp blocks, 3-deep cp.async
// pipeline, 32-box tiles interleaved across warps, one lane per box,
// smem-cached anchors, packed float4 streaming output stores.
// Inputs: small [104,104,3,85] f32, middle [208,208,3,85] f32,
//         large [416,416,3,85] f32, pre_scale [6,3,2] f32.
// Output: [681408, 6] f32, rows zeroed where conf <= 0.5.

constexpr int N_SMALL  = 104 * 104 * 3;   // 32448  (mult of 32)
constexpr int N_MIDDLE = 208 * 208 * 3;   // 129792 (mult of 32)
constexpr int N_LARGE  = 416 * 416 * 3;   // 519168 (mult of 32)
constexpr int N_TOTAL  = N_SMALL + N_MIDDLE + N_LARGE;  // 681408
constexpr int TILE     = 32;
constexpr int N_TILES  = N_TOTAL / TILE;  // 21294
constexpr int NBLK     = 148 * 6;         // 888 single-warp blocks, 6/SM
constexpr int TOTW     = NBLK;            // 888 warps, ~24 tiles each
constexpr int V4T      = TILE * 85 / 4;   // 680 float4 per tile = 21*32 + 8
constexpr int D        = 3;               // pipeline depth (buffers/warp)

static __device__ __forceinline__ void cp16(uint32_t dst_smem, const float4* src) {
    asm volatile("cp.async.cg.shared.global [%0], [%1], 16;\n"
                 :: "r"(dst_smem), "l"(src));
}
static __device__ __forceinline__ void cp_commit() {
    asm volatile("cp.async.commit_group;\n" ::: "memory");
}
template<int N>
static __device__ __forceinline__ void cp_wait() {
    asm volatile("cp.async.wait_group %0;\n" :: "n"(N) : "memory");
}

static __device__ __forceinline__ void tile_level(
    int t, const float* small, const float* middle, const float* large,
    const float*& in, int& lvl, int& r0)
{
    const int boxBase = t * TILE;
    if (boxBase < N_SMALL)                 { in = small;  lvl = 0; r0 = boxBase; }
    else if (boxBase < N_SMALL + N_MIDDLE) { in = middle; lvl = 1; r0 = boxBase - N_SMALL; }
    else                                   { in = large;  lvl = 2; r0 = boxBase - N_SMALL - N_MIDDLE; }
}

template<int S, int DECT>
static __device__ __forceinline__ void boxxform(
    int r, float tx, float ty, float tw, float th,
    const float* __restrict__ ps_sm,     // smem-cached [6,3,2] anchor table
    float& x, float& y, float& w, float& h)
{
    const int i = r / (3 * S);
    const int j = (r / 3) % S;
    const int a = r % 3;
    constexpr float invS = 1.0f / (float)S;
    x = (1.0f / (1.0f + __expf(-tx)) + (float)i) * invS;
    y = (1.0f / (1.0f + __expf(-ty)) + (float)j) * invS;
    const float aw = ps_sm[(DECT * 3 + a) * 2 + 0];
    const float ah = ps_sm[(DECT * 3 + a) * 2 + 1];
    w = __expf(tw) * aw * (1.0f / 416.0f);
    h = __expf(th) * ah * (1.0f / 416.0f);
}

// merge two (val, idx) argmax candidates; smallest index wins ties
static __device__ __forceinline__ void amerge(float& av, int& ai, float bv, int bi) {
    if (bv > av || (bv == av && bi < ai)) { av = bv; ai = bi; }
}

__global__ __launch_bounds__(32) void HEAD_kernel(
    const float* __restrict__ small,
    const float* __restrict__ middle,
    const float* __restrict__ large,
    const float* __restrict__ pre_scale,
    float* __restrict__ out)
{
    __shared__ float4 sm[D][V4T];        // 32640 B
    __shared__ float  so[TILE * 6];      //   768 B output staging
    __shared__ float  sps[36];           // pre_scale cache [6,3,2]

    const int lane = threadIdx.x;
    const int gw   = blockIdx.x;

    // cache the anchor table once
    sps[lane] = __ldg(pre_scale + lane);
    if (lane < 4) sps[32 + lane] = __ldg(pre_scale + 32 + lane);
    __syncwarp();

    uint32_t sbase[D];
    #pragma unroll
    for (int k = 0; k < D; k++)
        sbase[k] = (uint32_t)__cvta_generic_to_shared(&sm[k][0]);

    // stage one tile's copies into buffer `buf`; ALWAYS commits ONE group
    auto stage = [&](int t, int buf) {
        if (t < N_TILES) {
            const float* in; int lvl, r0;
            tile_level(t, small, middle, large, in, lvl, r0);
            const float4* g4 = (const float4*)(in + (size_t)r0 * 85);
            const uint32_t sb = sbase[buf];
            #pragma unroll
            for (int j = 0; j < 21; j++) {           // 21 full rounds, no guard
                const int idx = lane + 32 * j;
                cp16(sb + idx * 16, g4 + idx);
            }
            if (lane < 8) {                          // tail: idx 672..679
                const int idx = 672 + lane;
                cp16(sb + idx * 16, g4 + idx);
            }
        }
        cp_commit();
    };

    auto compute = [&](int t, int buf) {
        const float* inu; int lvl, r0;
        tile_level(t, small, middle, large, inu, lvl, r0);

        const float* b = (const float*)&sm[buf][0] + lane * 85;
        const float conf = b[0];
        const float tx = b[1], ty = b[2], tw = b[3], th = b[4];

        // 4-chain argmax over 80 logits (indices 5..84), first-occurrence ties
        float v0 = b[5], v1 = b[6], v2 = b[7], v3 = b[8];
        int   j0 = 0,    j1 = 1,    j2 = 2,    j3 = 3;
        #pragma unroll
        for (int k = 4; k < 80; k += 4) {
            const float a0 = b[5 + k];
            const float a1 = b[6 + k];
            const float a2 = b[7 + k];
            const float a3 = b[8 + k];
            if (a0 > v0) { v0 = a0; j0 = k; }
            if (a1 > v1) { v1 = a1; j1 = k + 1; }
            if (a2 > v2) { v2 = a2; j2 = k + 2; }
            if (a3 > v3) { v3 = a3; j3 = k + 3; }
        }
        amerge(v0, j0, v1, j1);
        amerge(v2, j2, v3, j3);
        amerge(v0, j0, v2, j2);
        const int bi = j0;

        const int r = r0 + lane;
        float x, y, w, h;
        if (lvl == 0)      boxxform<104, 3>(r, tx, ty, tw, th, sps, x, y, w, h);
        else if (lvl == 1) boxxform<208, 4>(r, tx, ty, tw, th, sps, x, y, w, h);
        else               boxxform<416, 5>(r, tx, ty, tw, th, sps, x, y, w, h);

        const float mk = (conf > 0.5f) ? 1.0f : 0.0f;
        float* o = &so[lane * 6];
        o[0] = x * mk;
        o[1] = y * mk;
        o[2] = w * mk;
        o[3] = h * mk;
        o[4] = (float)bi * mk;
        o[5] = conf * mk;
        __syncwarp();
        // 32 boxes * 6 floats = 48 float4 -> two coalesced streaming rounds
        float4* og = (float4*)(out + (size_t)t * (TILE * 6));
        __stcs(og + lane, ((const float4*)so)[lane]);
        if (lane < 16) __stcs(og + 32 + lane, ((const float4*)so)[32 + lane]);
    };

    const int t0 = gw;

    #pragma unroll
    for (int k = 0; k < D - 1; k++) stage(t0 + k * TOTW, k);

    int i = 0;
    for (int t = t0; t < N_TILES; t += TOTW, i++) {
        cp_wait<D - 2>();                // tile t's group complete
        __syncwarp();                    // converge + prev-iter smem reuse
        compute(t, i % D);
        stage(t + (D - 1) * TOTW, (i + D - 1) % D);  // refill oldest buffer
    }
}

extern "C" void kernel_launch(void* const* d_in, const int* in_sizes, int n_in,
                              void* d_out, int out_size)
{
    const float* small     = (const float*)d_in[0];
    const float* middle    = (const float*)d_in[1];
    const float* large     = (const float*)d_in[2];
    const float* pre_scale = (const float*)d_in[3];
    float* out = (float*)d_out;

    HEAD_kernel<<<NBLK, 32>>>(small, middle, large, pre_scale, out);
}